// round 10
// baseline (speedup 1.0000x reference)
#include <cuda_runtime.h>
#include <cstdint>

namespace {

constexpr int kB = 64;
constexpr int kN = 8;
constexpr int kV = 128000;
constexpr int kTPB = 128;
constexpr int kF4 = kV / 4;                 // 32000 float4 per row
constexpr int kChB = 18;                    // chunks per bonus row
constexpr int kChR = 19;                    // chunks per recover row
constexpr int kBonusBlocks = kB * kChB;     // 1152
constexpr int kGrid = kBonusBlocks + kB * kChR;  // 2368 = 148 SMs x 16 blocks
constexpr int kIters = 7;                   // ceil(1778/256) = ceil(1685/256) = 7

// packed argmax: (float_bits << 32) | ~index  -> atomicMax == (max val, tie: min idx)
__device__ unsigned long long g_best[2 * kB];
__device__ unsigned g_ticket;

__device__ __forceinline__ float neg_inf() { return __int_as_float(0xff800000); }

// ---------------- JAX threefry2x32 (exact round structure) -------------------------
__device__ __forceinline__ void tfround(uint32_t& x0, uint32_t& x1, int r) {
  x0 += x1;
  x1 = __funnelshift_l(x1, x1, r);
  x1 ^= x0;
}

__device__ __forceinline__ uint2 threefry2x32(uint32_t k0, uint32_t k1,
                                              uint32_t x0, uint32_t x1) {
  uint32_t k2 = k0 ^ k1 ^ 0x1BD11BDAu;
  x0 += k0; x1 += k1;
  tfround(x0, x1, 13); tfround(x0, x1, 15); tfround(x0, x1, 26); tfround(x0, x1, 6);
  x0 += k1; x1 += k2 + 1u;
  tfround(x0, x1, 17); tfround(x0, x1, 29); tfround(x0, x1, 16); tfround(x0, x1, 24);
  x0 += k2; x1 += k0 + 2u;
  tfround(x0, x1, 13); tfround(x0, x1, 15); tfround(x0, x1, 26); tfround(x0, x1, 6);
  x0 += k0; x1 += k1 + 3u;
  tfround(x0, x1, 17); tfround(x0, x1, 29); tfround(x0, x1, 16); tfround(x0, x1, 24);
  x0 += k1; x1 += k2 + 4u;
  tfround(x0, x1, 13); tfround(x0, x1, 15); tfround(x0, x1, 26); tfround(x0, x1, 6);
  x0 += k2; x1 += k0 + 5u;
  return make_uint2(x0, x1);
}

__device__ __forceinline__ uint32_t rbits32(uint2 key, uint32_t idx) {
  uint2 o = threefry2x32(key.x, key.y, 0u, idx);
  return o.x ^ o.y;
}

__device__ __forceinline__ float uni01(uint32_t bits) {
  return __uint_as_float((bits >> 9) | 0x3f800000u) - 1.0f;
}

// t = -log(u), u = B-1, B in [1,2). Dual path (validated rel_err 0.0 in R8):
//   d = 2-B <= 0.125: degree-6 Taylor of -log(1-d)/d, rel err ~3e-7.
//   else: -__logf(u), t >= 0.1335 -> rel err <= 1.3e-6. u==0 -> t=+inf -> val 0.
__device__ __forceinline__ float tval(uint2 key, uint32_t idx) {
  uint32_t bits = rbits32(key, idx);
  float B = __uint_as_float((bits >> 9) | 0x3f800000u);
  float u = B - 1.0f;
  float d = 2.0f - B;
  float p = 0.14285714f;
  p = fmaf(p, d, 0.16666667f);
  p = fmaf(p, d, 0.2f);
  p = fmaf(p, d, 0.25f);
  p = fmaf(p, d, 0.33333333f);
  p = fmaf(p, d, 0.5f);
  p = fmaf(p, d, 1.0f);
  float ts = d * p;
  float tb = -__logf(u);
  return (d <= 0.125f) ? ts : tb;
}

struct BestPair { float v; int i; };

// Strict-'>' pairwise tree over 8 candidates: v[0..3] -> iA+{0..3},
// v[4..7] -> iB+{0..3}, iA+3 < iB. Lowest index wins ties at every level.
// Masked (-inf) candidates can never be selected.
__device__ __forceinline__ void upd8(BestPair& best, const float* v, int iA, int iB) {
  float a0 = v[0]; int j0 = iA;
  if (v[1] > a0) { a0 = v[1]; j0 = iA + 1; }
  float a1 = v[2]; int j1 = iA + 2;
  if (v[3] > a1) { a1 = v[3]; j1 = iA + 3; }
  float a2 = v[4]; int j2 = iB;
  if (v[5] > a2) { a2 = v[5]; j2 = iB + 1; }
  float a3 = v[6]; int j3 = iB + 2;
  if (v[7] > a3) { a3 = v[7]; j3 = iB + 3; }
  if (a1 > a0) { a0 = a1; j0 = j1; }
  if (a3 > a2) { a2 = a3; j2 = j3; }
  if (a2 > a0) { a0 = a2; j0 = j2; }
  if (a0 > best.v) { best.v = a0; best.i = j0; }
}

// Block argmax (128 threads, tie-break min index); thread 0 holds the result.
__device__ __forceinline__ BestPair block_argmax(BestPair best) {
  __shared__ float sv[4];
  __shared__ int   si[4];
  unsigned full = 0xffffffffu;
#pragma unroll
  for (int off = 16; off > 0; off >>= 1) {
    float ov = __shfl_down_sync(full, best.v, off);
    int   oi = __shfl_down_sync(full, best.i, off);
    if (ov > best.v || (ov == best.v && oi < best.i)) { best.v = ov; best.i = oi; }
  }
  int warp = threadIdx.x >> 5;
  int lane = threadIdx.x & 31;
  if (lane == 0) { sv[warp] = best.v; si[warp] = best.i; }
  __syncthreads();
  if (threadIdx.x == 0) {
#pragma unroll
    for (int w = 1; w < 4; w++) {
      if (sv[w] > best.v || (sv[w] == best.v && si[w] < best.i)) {
        best.v = sv[w]; best.i = si[w];
      }
    }
  }
  return best;
}

// accept decision for (b, n)
__device__ __forceinline__ bool accept_bn(int b, int n, const int* __restrict__ tok,
                                          const float* __restrict__ dp,
                                          const float* __restrict__ vp) {
  uint2 ku = threefry2x32(0u, 1u, 0u, 0u);   // split(key(1),3)[0] — const-folded
  int L = b * kN + n;
  float u = uni01(rbits32(ku, (uint32_t)L));
  int t = tok[L];
  t = min(max(t, 0), kV - 1);
  float q = dp[(size_t)L * kV + t];
  float p = vp[((size_t)b * (kN + 1) + n) * kV + t];
  return (u * q < p);
}

// ---------------- Single mega kernel: grid == exactly one resident wave ------------
// blocks [0, 1152):     bonus    row b = blk/18, chunk c = blk%18  (span of 32000/18)
// blocks [1152, 2368):  recover  row b = blk'/19, chunk c = blk'%19 (span of 32000/19)
// Last block (ticket) merges g_best, computes acc/em, writes output, resets scratch.
__global__ __launch_bounds__(kTPB, 16)
void kGumbel(const int* __restrict__ tok, const float* __restrict__ dp,
             const float* __restrict__ vp, float* __restrict__ out, int out_size) {
  int blk = blockIdx.x;
  int t = threadIdx.x;
  bool is_bonus = blk < kBonusBlocks;

  BestPair best = {neg_inf(), 0x7fffffff};
  int rowSlot;   // index into g_best

  if (is_bonus) {
    int b = blk / kChB;
    int c = blk - b * kChB;
    rowSlot = b;
    int beg = c * kF4 / kChB;
    int end = (c + 1) * kF4 / kChB;
    uint2 kb = threefry2x32(0u, 1u, 0u, 2u);   // subkey 2 (const-folded)
    const float4* row = (const float4*)(vp + ((size_t)b * (kN + 1) + kN) * kV);
    uint32_t Lbase = (uint32_t)b * (uint32_t)kV;   // gumbel shape (B, V)
#pragma unroll
    for (int k = 0; k < kIters; k++) {
      int i0 = beg + k * 2 * kTPB + t;
      int i1 = i0 + kTPB;
      bool ok0 = i0 < end, ok1 = i1 < end;
      float vals[8];
      if (ok0) {
        float4 pa = row[i0];
        vals[0] = __fdividef(pa.x, tval(kb, Lbase + 4 * i0 + 0));
        vals[1] = __fdividef(pa.y, tval(kb, Lbase + 4 * i0 + 1));
        vals[2] = __fdividef(pa.z, tval(kb, Lbase + 4 * i0 + 2));
        vals[3] = __fdividef(pa.w, tval(kb, Lbase + 4 * i0 + 3));
      } else {
        vals[0] = vals[1] = vals[2] = vals[3] = neg_inf();
      }
      if (ok1) {
        float4 pb = row[i1];
        vals[4] = __fdividef(pb.x, tval(kb, Lbase + 4 * i1 + 0));
        vals[5] = __fdividef(pb.y, tval(kb, Lbase + 4 * i1 + 1));
        vals[6] = __fdividef(pb.z, tval(kb, Lbase + 4 * i1 + 2));
        vals[7] = __fdividef(pb.w, tval(kb, Lbase + 4 * i1 + 3));
      } else {
        vals[4] = vals[5] = vals[6] = vals[7] = neg_inf();
      }
      upd8(best, vals, 4 * i0, 4 * i1);
    }
  } else {
    int rb = blk - kBonusBlocks;
    int b = rb / kChR;
    int c = rb - b * kChR;
    rowSlot = kB + b;
    __shared__ int s_em;
    if (t < 8) {
      bool acc = accept_bn(b, t, tok, dp, vp);
      unsigned m = __ballot_sync(0xffu, acc);
      if (t == 0) s_em = __ffs((~m) & 0x1FF) - 1;
    }
    __syncthreads();
    int em = s_em;
    if (em < kN) {
      int beg = c * kF4 / kChR;
      int end = (c + 1) * kF4 / kChR;
      uint2 kr = threefry2x32(0u, 1u, 0u, 1u);   // subkey 1 (const-folded)
      const float4* drow = (const float4*)(dp + ((size_t)b * kN + em) * kV);
      const float4* vrow = (const float4*)(vp + ((size_t)b * (kN + 1) + em) * kV);
      uint32_t Lbase = (uint32_t)(b * kN + em) * (uint32_t)kV;   // shape (B, N, V)
#pragma unroll
      for (int k = 0; k < kIters; k++) {
        int i0 = beg + k * 2 * kTPB + t;
        int i1 = i0 + kTPB;
        bool ok0 = i0 < end, ok1 = i1 < end;
        float vals[8];
        if (ok0) {
          float4 da = drow[i0];
          float4 va = vrow[i0];
          vals[0] = __fdividef(fmaxf(va.x - da.x, 0.0f), tval(kr, Lbase + 4 * i0 + 0));
          vals[1] = __fdividef(fmaxf(va.y - da.y, 0.0f), tval(kr, Lbase + 4 * i0 + 1));
          vals[2] = __fdividef(fmaxf(va.z - da.z, 0.0f), tval(kr, Lbase + 4 * i0 + 2));
          vals[3] = __fdividef(fmaxf(va.w - da.w, 0.0f), tval(kr, Lbase + 4 * i0 + 3));
        } else {
          vals[0] = vals[1] = vals[2] = vals[3] = neg_inf();
        }
        if (ok1) {
          float4 db = drow[i1];
          float4 vb = vrow[i1];
          vals[4] = __fdividef(fmaxf(vb.x - db.x, 0.0f), tval(kr, Lbase + 4 * i1 + 0));
          vals[5] = __fdividef(fmaxf(vb.y - db.y, 0.0f), tval(kr, Lbase + 4 * i1 + 1));
          vals[6] = __fdividef(fmaxf(vb.z - db.z, 0.0f), tval(kr, Lbase + 4 * i1 + 2));
          vals[7] = __fdividef(fmaxf(vb.w - db.w, 0.0f), tval(kr, Lbase + 4 * i1 + 3));
        } else {
          vals[4] = vals[5] = vals[6] = vals[7] = neg_inf();
        }
        upd8(best, vals, 4 * i0, 4 * i1);
      }
    }
  }

  // ---- merge block result into global packed argmax ------------------------------
  best = block_argmax(best);
  if (t == 0 && best.i != 0x7fffffff) {
    unsigned long long packed =
        ((unsigned long long)__float_as_uint(best.v) << 32) | (unsigned)(~best.i);
    atomicMax(&g_best[rowSlot], packed);
  }

  // ---- deterministic last-block final assembly -----------------------------------
  __threadfence();
  __shared__ bool amLast;
  if (t == 0) {
    unsigned tk = atomicAdd(&g_ticket, 1u);
    amLast = (tk == (unsigned)(kGrid - 1));
  }
  __syncthreads();
  if (!amLast) return;

  volatile unsigned long long* vbest = g_best;
  int bb = t;
  if (bb < kB) {
    int acc = 0, em = 0;
    bool alive = true;
#pragma unroll
    for (int n = 0; n < kN; n++) {
      bool a = accept_bn(bb, n, tok, dp, vp);
      acc += a ? 1 : 0;
      if (alive) { if (a) em++; else alive = false; }
    }
    if (out_size >= kB * (kN + 1) + 2 * kB) {
      out[kB * (kN + 1) + bb] = (float)acc;
      out[kB * (kN + 1) + kB + bb] = (float)em;
    }
    unsigned long long packedB = vbest[bb];
    unsigned long long packedR = vbest[kB + bb];
    int fin = (em < kN) ? (int)(~(unsigned)(packedR & 0xffffffffu))
                        : (int)(~(unsigned)(packedB & 0xffffffffu));
#pragma unroll
    for (int pos = 0; pos < kN + 1; pos++) {
      float o;
      if (pos < em)       o = (float)tok[bb * kN + pos];
      else if (pos == em) o = (float)fin;
      else                o = -1.0f;
      out[bb * (kN + 1) + pos] = o;
    }
  }
  __syncthreads();
  // reset scratch for the next graph replay
  if (t < 2 * kB) g_best[t] = 0ull;
  if (t == 0) g_ticket = 0u;
}

}  // namespace

extern "C" void kernel_launch(void* const* d_in, const int* in_sizes, int n_in,
                              void* d_out, int out_size) {
  const int*   tok = nullptr;
  const float* dp  = nullptr;
  const float* vp  = nullptr;
  for (int i = 0; i < n_in; i++) {
    if (in_sizes[i] == kB * kN)                      tok = (const int*)d_in[i];
    else if (in_sizes[i] == kB * kN * kV)            dp  = (const float*)d_in[i];
    else if (in_sizes[i] == kB * (kN + 1) * kV)      vp  = (const float*)d_in[i];
  }
  float* out = (float*)d_out;

  kGumbel<<<kGrid, kTPB>>>(tok, dp, vp, out, out_size);
}

// round 12
// speedup vs baseline: 1.5737x; 1.5737x over previous
#include <cuda_runtime.h>
#include <cstdint>

namespace {

constexpr int kB = 64;
constexpr int kN = 8;
constexpr int kV = 128000;
constexpr int kCH = 25;                 // chunks per row; kQ4 = 1280 = 5 * 2 * 128
constexpr int kQ4 = kV / kCH / 4;       // float4s per chunk = 1280
constexpr int kTPB = 128;
constexpr int kPairIters = kQ4 / (2 * kTPB);  // 5, exact
constexpr int kBonusBlocks = kB * kCH;        // 1600
constexpr int kGridTotal   = 2 * kB * kCH;    // 3200

// packed argmax: (float_bits << 32) | ~index -> atomicMax == (max val, tie: min idx)
// slots [0,64): bonus rows, [64,128): recover rows
__device__ unsigned long long g_best[2 * kB];
__device__ unsigned g_ticket;

__device__ __forceinline__ float neg_inf() { return __int_as_float(0xff800000); }

// ---------------- JAX threefry2x32 (exact round structure) -------------------------
__device__ __forceinline__ void tfround(uint32_t& x0, uint32_t& x1, int r) {
  x0 += x1;
  x1 = __funnelshift_l(x1, x1, r);
  x1 ^= x0;
}

__device__ __forceinline__ uint2 threefry2x32(uint32_t k0, uint32_t k1,
                                              uint32_t x0, uint32_t x1) {
  uint32_t k2 = k0 ^ k1 ^ 0x1BD11BDAu;
  x0 += k0; x1 += k1;
  tfround(x0, x1, 13); tfround(x0, x1, 15); tfround(x0, x1, 26); tfround(x0, x1, 6);
  x0 += k1; x1 += k2 + 1u;
  tfround(x0, x1, 17); tfround(x0, x1, 29); tfround(x0, x1, 16); tfround(x0, x1, 24);
  x0 += k2; x1 += k0 + 2u;
  tfround(x0, x1, 13); tfround(x0, x1, 15); tfround(x0, x1, 26); tfround(x0, x1, 6);
  x0 += k0; x1 += k1 + 3u;
  tfround(x0, x1, 17); tfround(x0, x1, 29); tfround(x0, x1, 16); tfround(x0, x1, 24);
  x0 += k1; x1 += k2 + 4u;
  tfround(x0, x1, 13); tfround(x0, x1, 15); tfround(x0, x1, 26); tfround(x0, x1, 6);
  x0 += k2; x1 += k0 + 5u;
  return make_uint2(x0, x1);
}

__device__ __forceinline__ uint32_t rbits32(uint2 key, uint32_t idx) {
  uint2 o = threefry2x32(key.x, key.y, 0u, idx);
  return o.x ^ o.y;
}

__device__ __forceinline__ float uni01(uint32_t bits) {
  return __uint_as_float((bits >> 9) | 0x3f800000u) - 1.0f;
}

// t = -log(u), u = B-1, B in [1,2). Dual path (validated rel_err 0.0 in R8-R10):
//   d = 2-B <= 0.125: degree-6 Taylor of -log(1-d)/d, rel err ~3e-7.
//   else: -__logf(u), t >= 0.1335 -> rel err <= 1.3e-6. u==0 -> t=+inf -> val 0.
__device__ __forceinline__ float tval(uint2 key, uint32_t idx) {
  uint32_t bits = rbits32(key, idx);
  float B = __uint_as_float((bits >> 9) | 0x3f800000u);
  float u = B - 1.0f;
  float d = 2.0f - B;
  float p = 0.14285714f;
  p = fmaf(p, d, 0.16666667f);
  p = fmaf(p, d, 0.2f);
  p = fmaf(p, d, 0.25f);
  p = fmaf(p, d, 0.33333333f);
  p = fmaf(p, d, 0.5f);
  p = fmaf(p, d, 1.0f);
  float ts = d * p;
  float tb = -__logf(u);
  return (d <= 0.125f) ? ts : tb;
}

struct BestPair { float v; int i; };

// Strict-'>' pairwise tree over 8 candidates: v[0..3] -> iA+{0..3},
// v[4..7] -> iB+{0..3}, iA+3 < iB. Lowest index wins ties at every level.
__device__ __forceinline__ void upd8(BestPair& best, const float* v, int iA, int iB) {
  float a0 = v[0]; int j0 = iA;
  if (v[1] > a0) { a0 = v[1]; j0 = iA + 1; }
  float a1 = v[2]; int j1 = iA + 2;
  if (v[3] > a1) { a1 = v[3]; j1 = iA + 3; }
  float a2 = v[4]; int j2 = iB;
  if (v[5] > a2) { a2 = v[5]; j2 = iB + 1; }
  float a3 = v[6]; int j3 = iB + 2;
  if (v[7] > a3) { a3 = v[7]; j3 = iB + 3; }
  if (a1 > a0) { a0 = a1; j0 = j1; }
  if (a3 > a2) { a2 = a3; j2 = j3; }
  if (a2 > a0) { a0 = a2; j0 = j2; }
  if (a0 > best.v) { best.v = a0; best.i = j0; }
}

// Block argmax (128 threads, tie-break min index); thread 0 holds the result.
__device__ __forceinline__ BestPair block_argmax(BestPair best) {
  __shared__ float sv[4];
  __shared__ int   si[4];
  unsigned full = 0xffffffffu;
#pragma unroll
  for (int off = 16; off > 0; off >>= 1) {
    float ov = __shfl_down_sync(full, best.v, off);
    int   oi = __shfl_down_sync(full, best.i, off);
    if (ov > best.v || (ov == best.v && oi < best.i)) { best.v = ov; best.i = oi; }
  }
  int warp = threadIdx.x >> 5;
  int lane = threadIdx.x & 31;
  if (lane == 0) { sv[warp] = best.v; si[warp] = best.i; }
  __syncthreads();
  if (threadIdx.x == 0) {
#pragma unroll
    for (int w = 1; w < 4; w++) {
      if (sv[w] > best.v || (sv[w] == best.v && si[w] < best.i)) {
        best.v = sv[w]; best.i = si[w];
      }
    }
  }
  return best;
}

// accept decision for (b, n)
__device__ __forceinline__ bool accept_bn(int b, int n, const int* __restrict__ tok,
                                          const float* __restrict__ dp,
                                          const float* __restrict__ vp) {
  uint2 ku = threefry2x32(0u, 1u, 0u, 0u);   // split(key(1),3)[0] — const-folded
  int L = b * kN + n;
  float u = uni01(rbits32(ku, (uint32_t)L));
  int t = tok[L];
  t = min(max(t, 0), kV - 1);
  float q = dp[(size_t)L * kV + t];
  float p = vp[((size_t)b * (kN + 1) + n) * kV + t];
  return (u * q < p);
}

// em for batch b, computed by lanes 0..7 + ballot; all threads get the value.
__device__ __forceinline__ int compute_em(int b, const int* __restrict__ tok,
                                          const float* __restrict__ dp,
                                          const float* __restrict__ vp,
                                          int* s_em) {
  if (threadIdx.x < 8) {
    bool acc = accept_bn(b, threadIdx.x, tok, dp, vp);
    unsigned m = __ballot_sync(0xffu, acc);
    if (threadIdx.x == 0) *s_em = __ffs((~m) & 0x1FF) - 1;  // count of leading accepts
  }
  __syncthreads();
  return *s_em;
}

// ---------------- Single mega kernel (R8 skeleton + bonus em-gate) -----------------
// blocks [0, 1600):     bonus    (b = rb/25, c = rb%25) — ACTIVE ONLY IF em[b]==8
// blocks [1600, 3200):  recover  (active only if em[b] < 8)
// Expected active rows ~64 of 128 -> total work nearly halves.
__global__ void kGumbel(const int* __restrict__ tok, const float* __restrict__ dp,
                        const float* __restrict__ vp, float* __restrict__ out,
                        int out_size) {
  __shared__ int s_em;
  int blk = blockIdx.x;
  bool is_bonus = blk < kBonusBlocks;
  int rb = is_bonus ? blk : blk - kBonusBlocks;
  int b = rb / kCH;
  int c = rb % kCH;
  int t = threadIdx.x;

  BestPair best = {neg_inf(), 0x7fffffff};
  int em = compute_em(b, tok, dp, vp, &s_em);

  if (is_bonus) {
    if (em >= kN) {      // bonus consumed only when all 8 drafts accepted
      uint2 kb = threefry2x32(0u, 1u, 0u, 2u);   // subkey 2 (const-folded)
      const float4* row = (const float4*)(vp + ((size_t)b * (kN + 1) + kN) * kV);
      uint32_t Lbase = (uint32_t)b * (uint32_t)kV;   // gumbel shape (B, V)
      int base = c * kQ4 + t;
#pragma unroll 1
      for (int k = 0; k < kPairIters; k++) {
        int i0 = base + k * 2 * kTPB;
        int i1 = i0 + kTPB;
        float4 pa = row[i0];
        float4 pb = row[i1];
        float vals[8];
        vals[0] = __fdividef(pa.x, tval(kb, Lbase + 4 * i0 + 0));
        vals[1] = __fdividef(pa.y, tval(kb, Lbase + 4 * i0 + 1));
        vals[2] = __fdividef(pa.z, tval(kb, Lbase + 4 * i0 + 2));
        vals[3] = __fdividef(pa.w, tval(kb, Lbase + 4 * i0 + 3));
        vals[4] = __fdividef(pb.x, tval(kb, Lbase + 4 * i1 + 0));
        vals[5] = __fdividef(pb.y, tval(kb, Lbase + 4 * i1 + 1));
        vals[6] = __fdividef(pb.z, tval(kb, Lbase + 4 * i1 + 2));
        vals[7] = __fdividef(pb.w, tval(kb, Lbase + 4 * i1 + 3));
        upd8(best, vals, 4 * i0, 4 * i1);
      }
      best = block_argmax(best);
      if (t == 0 && best.i != 0x7fffffff) {
        unsigned long long packed =
            ((unsigned long long)__float_as_uint(best.v) << 32) | (unsigned)(~best.i);
        atomicMax(&g_best[b], packed);
      }
    }
  } else {
    if (em < kN) {
      uint2 kr = threefry2x32(0u, 1u, 0u, 1u);   // subkey 1 (const-folded)
      const float4* drow = (const float4*)(dp + ((size_t)b * kN + em) * kV);
      const float4* vrow = (const float4*)(vp + ((size_t)b * (kN + 1) + em) * kV);
      uint32_t Lbase = (uint32_t)(b * kN + em) * (uint32_t)kV;   // shape (B, N, V)
      int base = c * kQ4 + t;
#pragma unroll 1
      for (int k = 0; k < kPairIters; k++) {
        int i0 = base + k * 2 * kTPB;
        int i1 = i0 + kTPB;
        float4 da = drow[i0];
        float4 va = vrow[i0];
        float4 db = drow[i1];
        float4 vb = vrow[i1];
        float vals[8];
        vals[0] = __fdividef(fmaxf(va.x - da.x, 0.0f), tval(kr, Lbase + 4 * i0 + 0));
        vals[1] = __fdividef(fmaxf(va.y - da.y, 0.0f), tval(kr, Lbase + 4 * i0 + 1));
        vals[2] = __fdividef(fmaxf(va.z - da.z, 0.0f), tval(kr, Lbase + 4 * i0 + 2));
        vals[3] = __fdividef(fmaxf(va.w - da.w, 0.0f), tval(kr, Lbase + 4 * i0 + 3));
        vals[4] = __fdividef(fmaxf(vb.x - db.x, 0.0f), tval(kr, Lbase + 4 * i1 + 0));
        vals[5] = __fdividef(fmaxf(vb.y - db.y, 0.0f), tval(kr, Lbase + 4 * i1 + 1));
        vals[6] = __fdividef(fmaxf(vb.z - db.z, 0.0f), tval(kr, Lbase + 4 * i1 + 2));
        vals[7] = __fdividef(fmaxf(vb.w - db.w, 0.0f), tval(kr, Lbase + 4 * i1 + 3));
        upd8(best, vals, 4 * i0, 4 * i1);
      }
      best = block_argmax(best);
      if (t == 0 && best.i != 0x7fffffff) {
        unsigned long long packed =
            ((unsigned long long)__float_as_uint(best.v) << 32) | (unsigned)(~best.i);
        atomicMax(&g_best[kB + b], packed);
      }
    }
  }

  // ---- deterministic last-block final assembly -----------------------------------
  __threadfence();
  __shared__ bool amLast;
  if (t == 0) {
    unsigned tk = atomicAdd(&g_ticket, 1u);
    amLast = (tk == (unsigned)(kGridTotal - 1));
  }
  __syncthreads();
  if (!amLast) return;

  volatile unsigned long long* vbest = g_best;
  int bb = t;
  if (bb < kB) {
    int acc = 0, em2 = 0;
    bool alive = true;
#pragma unroll
    for (int n = 0; n < kN; n++) {
      bool a = accept_bn(bb, n, tok, dp, vp);
      acc += a ? 1 : 0;
      if (alive) { if (a) em2++; else alive = false; }
    }
    if (out_size >= kB * (kN + 1) + 2 * kB) {
      out[kB * (kN + 1) + bb] = (float)acc;
      out[kB * (kN + 1) + kB + bb] = (float)em2;
    }
    unsigned long long packedB = vbest[bb];
    unsigned long long packedR = vbest[kB + bb];
    int fin = (em2 < kN) ? (int)(~(unsigned)(packedR & 0xffffffffu))
                         : (int)(~(unsigned)(packedB & 0xffffffffu));
#pragma unroll
    for (int pos = 0; pos < kN + 1; pos++) {
      float o;
      if (pos < em2)       o = (float)tok[bb * kN + pos];
      else if (pos == em2) o = (float)fin;
      else                 o = -1.0f;
      out[bb * (kN + 1) + pos] = o;
    }
  }
  __syncthreads();
  // reset scratch for the next graph replay
  if (t < 2 * kB) g_best[t] = 0ull;
  if (t == 0) g_ticket = 0u;
}

}  // namespace

extern "C" void kernel_launch(void* const* d_in, const int* in_sizes, int n_in,
                              void* d_out, int out_size) {
  const int*   tok = nullptr;
  const float* dp  = nullptr;
  const float* vp  = nullptr;
  for (int i = 0; i < n_in; i++) {
    if (in_sizes[i] == kB * kN)                      tok = (const int*)d_in[i];
    else if (in_sizes[i] == kB * kN * kV)            dp  = (const float*)d_in[i];
    else if (in_sizes[i] == kB * (kN + 1) * kV)      vp  = (const float*)d_in[i];
  }
  float* out = (float*)d_out;

  kGumbel<<<kGridTotal, kTPB>>>(tok, dp, vp, out, out_size);
}

// round 13
// speedup vs baseline: 2.0256x; 1.2871x over previous
#include <cuda_runtime.h>
#include <cstdint>

namespace {

constexpr int kB = 64;
constexpr int kN = 8;
constexpr int kV = 128000;
constexpr int kCH = 25;                 // chunks per row; kQ4 = 1280 = 5 * 2 * 128
constexpr int kQ4 = kV / kCH / 4;       // float4s per chunk = 1280
constexpr int kTPB = 128;
constexpr int kPairIters = kQ4 / (2 * kTPB);  // 5, exact
constexpr int kGridTotal = kB * kCH;          // 1600 — every block fully active

// packed argmax: (float_bits << 32) | ~index -> atomicMax == (max val, tie: min idx)
// slot b: the single argmax each batch needs (bonus if em==8, else recover)
__device__ unsigned long long g_best[kB];
__device__ unsigned g_ticket;

__device__ __forceinline__ float neg_inf() { return __int_as_float(0xff800000); }

// ---------------- JAX threefry2x32 (exact round structure) -------------------------
__device__ __forceinline__ void tfround(uint32_t& x0, uint32_t& x1, int r) {
  x0 += x1;
  x1 = __funnelshift_l(x1, x1, r);
  x1 ^= x0;
}

__device__ __forceinline__ uint2 threefry2x32(uint32_t k0, uint32_t k1,
                                              uint32_t x0, uint32_t x1) {
  uint32_t k2 = k0 ^ k1 ^ 0x1BD11BDAu;
  x0 += k0; x1 += k1;
  tfround(x0, x1, 13); tfround(x0, x1, 15); tfround(x0, x1, 26); tfround(x0, x1, 6);
  x0 += k1; x1 += k2 + 1u;
  tfround(x0, x1, 17); tfround(x0, x1, 29); tfround(x0, x1, 16); tfround(x0, x1, 24);
  x0 += k2; x1 += k0 + 2u;
  tfround(x0, x1, 13); tfround(x0, x1, 15); tfround(x0, x1, 26); tfround(x0, x1, 6);
  x0 += k0; x1 += k1 + 3u;
  tfround(x0, x1, 17); tfround(x0, x1, 29); tfround(x0, x1, 16); tfround(x0, x1, 24);
  x0 += k1; x1 += k2 + 4u;
  tfround(x0, x1, 13); tfround(x0, x1, 15); tfround(x0, x1, 26); tfround(x0, x1, 6);
  x0 += k2; x1 += k0 + 5u;
  return make_uint2(x0, x1);
}

__device__ __forceinline__ uint32_t rbits32(uint2 key, uint32_t idx) {
  uint2 o = threefry2x32(key.x, key.y, 0u, idx);
  return o.x ^ o.y;
}

__device__ __forceinline__ float uni01(uint32_t bits) {
  return __uint_as_float((bits >> 9) | 0x3f800000u) - 1.0f;
}

// t = -log(u), u = B-1, B in [1,2). Dual path (validated rel_err 0.0 since R8):
//   d = 2-B <= 0.125: degree-6 Taylor of -log(1-d)/d, rel err ~3e-7.
//   else: -__logf(u), t >= 0.1335 -> rel err <= 1.3e-6. u==0 -> t=+inf -> val 0.
__device__ __forceinline__ float tval(uint2 key, uint32_t idx) {
  uint32_t bits = rbits32(key, idx);
  float B = __uint_as_float((bits >> 9) | 0x3f800000u);
  float u = B - 1.0f;
  float d = 2.0f - B;
  float p = 0.14285714f;
  p = fmaf(p, d, 0.16666667f);
  p = fmaf(p, d, 0.2f);
  p = fmaf(p, d, 0.25f);
  p = fmaf(p, d, 0.33333333f);
  p = fmaf(p, d, 0.5f);
  p = fmaf(p, d, 1.0f);
  float ts = d * p;
  float tb = -__logf(u);
  return (d <= 0.125f) ? ts : tb;
}

struct BestPair { float v; int i; };

// Strict-'>' pairwise tree over 8 candidates: v[0..3] -> iA+{0..3},
// v[4..7] -> iB+{0..3}, iA+3 < iB. Lowest index wins ties at every level.
__device__ __forceinline__ void upd8(BestPair& best, const float* v, int iA, int iB) {
  float a0 = v[0]; int j0 = iA;
  if (v[1] > a0) { a0 = v[1]; j0 = iA + 1; }
  float a1 = v[2]; int j1 = iA + 2;
  if (v[3] > a1) { a1 = v[3]; j1 = iA + 3; }
  float a2 = v[4]; int j2 = iB;
  if (v[5] > a2) { a2 = v[5]; j2 = iB + 1; }
  float a3 = v[6]; int j3 = iB + 2;
  if (v[7] > a3) { a3 = v[7]; j3 = iB + 3; }
  if (a1 > a0) { a0 = a1; j0 = j1; }
  if (a3 > a2) { a2 = a3; j2 = j3; }
  if (a2 > a0) { a0 = a2; j0 = j2; }
  if (a0 > best.v) { best.v = a0; best.i = j0; }
}

// Block argmax (128 threads, tie-break min index); thread 0 holds the result.
__device__ __forceinline__ BestPair block_argmax(BestPair best) {
  __shared__ float sv[4];
  __shared__ int   si[4];
  unsigned full = 0xffffffffu;
#pragma unroll
  for (int off = 16; off > 0; off >>= 1) {
    float ov = __shfl_down_sync(full, best.v, off);
    int   oi = __shfl_down_sync(full, best.i, off);
    if (ov > best.v || (ov == best.v && oi < best.i)) { best.v = ov; best.i = oi; }
  }
  int warp = threadIdx.x >> 5;
  int lane = threadIdx.x & 31;
  if (lane == 0) { sv[warp] = best.v; si[warp] = best.i; }
  __syncthreads();
  if (threadIdx.x == 0) {
#pragma unroll
    for (int w = 1; w < 4; w++) {
      if (sv[w] > best.v || (sv[w] == best.v && si[w] < best.i)) {
        best.v = sv[w]; best.i = si[w];
      }
    }
  }
  return best;
}

// accept decision for (b, n)
__device__ __forceinline__ bool accept_bn(int b, int n, const int* __restrict__ tok,
                                          const float* __restrict__ dp,
                                          const float* __restrict__ vp) {
  uint2 ku = threefry2x32(0u, 1u, 0u, 0u);   // split(key(1),3)[0] — const-folded
  int L = b * kN + n;
  float u = uni01(rbits32(ku, (uint32_t)L));
  int t = tok[L];
  t = min(max(t, 0), kV - 1);
  float q = dp[(size_t)L * kV + t];
  float p = vp[((size_t)b * (kN + 1) + n) * kV + t];
  return (u * q < p);
}

// ---------------- Single mega kernel: one block per (batch, chunk), all active -----
// Block (b, c): compute em[b]; if em==8 run the bonus chunk, else the recover chunk.
// Exactly one argmax per batch is ever needed -> g_best has kB slots.
__global__ __launch_bounds__(kTPB, 16)
void kGumbel(const int* __restrict__ tok, const float* __restrict__ dp,
             const float* __restrict__ vp, float* __restrict__ out,
             int out_size) {
  __shared__ int s_em;
  int blk = blockIdx.x;
  int b = blk / kCH;
  int c = blk % kCH;
  int t = threadIdx.x;

  // em for this batch (lanes 0..7 + ballot)
  if (t < 8) {
    bool acc = accept_bn(b, t, tok, dp, vp);
    unsigned m = __ballot_sync(0xffu, acc);
    if (t == 0) s_em = __ffs((~m) & 0x1FF) - 1;
  }
  __syncthreads();
  int em = s_em;

  BestPair best = {neg_inf(), 0x7fffffff};
  int base = c * kQ4 + t;

  if (em >= kN) {
    // ---- bonus: argmax over verify[b, N, :] -------------------------------------
    uint2 kb = threefry2x32(0u, 1u, 0u, 2u);   // subkey 2 (const-folded)
    const float4* row = (const float4*)(vp + ((size_t)b * (kN + 1) + kN) * kV);
    uint32_t Lbase = (uint32_t)b * (uint32_t)kV;   // gumbel shape (B, V)
#pragma unroll 1
    for (int k = 0; k < kPairIters; k++) {
      int i0 = base + k * 2 * kTPB;
      int i1 = i0 + kTPB;
      float4 pa = row[i0];
      float4 pb = row[i1];
      float vals[8];
      vals[0] = __fdividef(pa.x, tval(kb, Lbase + 4 * i0 + 0));
      vals[1] = __fdividef(pa.y, tval(kb, Lbase + 4 * i0 + 1));
      vals[2] = __fdividef(pa.z, tval(kb, Lbase + 4 * i0 + 2));
      vals[3] = __fdividef(pa.w, tval(kb, Lbase + 4 * i0 + 3));
      vals[4] = __fdividef(pb.x, tval(kb, Lbase + 4 * i1 + 0));
      vals[5] = __fdividef(pb.y, tval(kb, Lbase + 4 * i1 + 1));
      vals[6] = __fdividef(pb.z, tval(kb, Lbase + 4 * i1 + 2));
      vals[7] = __fdividef(pb.w, tval(kb, Lbase + 4 * i1 + 3));
      upd8(best, vals, 4 * i0, 4 * i1);
    }
  } else {
    // ---- recover: argmax over relu(verify[b,em]-draft[b,em]) --------------------
    uint2 kr = threefry2x32(0u, 1u, 0u, 1u);   // subkey 1 (const-folded)
    const float4* drow = (const float4*)(dp + ((size_t)b * kN + em) * kV);
    const float4* vrow = (const float4*)(vp + ((size_t)b * (kN + 1) + em) * kV);
    uint32_t Lbase = (uint32_t)(b * kN + em) * (uint32_t)kV;   // shape (B, N, V)
#pragma unroll 1
    for (int k = 0; k < kPairIters; k++) {
      int i0 = base + k * 2 * kTPB;
      int i1 = i0 + kTPB;
      float4 da = drow[i0];
      float4 va = vrow[i0];
      float4 db = drow[i1];
      float4 vb = vrow[i1];
      float vals[8];
      vals[0] = __fdividef(fmaxf(va.x - da.x, 0.0f), tval(kr, Lbase + 4 * i0 + 0));
      vals[1] = __fdividef(fmaxf(va.y - da.y, 0.0f), tval(kr, Lbase + 4 * i0 + 1));
      vals[2] = __fdividef(fmaxf(va.z - da.z, 0.0f), tval(kr, Lbase + 4 * i0 + 2));
      vals[3] = __fdividef(fmaxf(va.w - da.w, 0.0f), tval(kr, Lbase + 4 * i0 + 3));
      vals[4] = __fdividef(fmaxf(vb.x - db.x, 0.0f), tval(kr, Lbase + 4 * i1 + 0));
      vals[5] = __fdividef(fmaxf(vb.y - db.y, 0.0f), tval(kr, Lbase + 4 * i1 + 1));
      vals[6] = __fdividef(fmaxf(vb.z - db.z, 0.0f), tval(kr, Lbase + 4 * i1 + 2));
      vals[7] = __fdividef(fmaxf(vb.w - db.w, 0.0f), tval(kr, Lbase + 4 * i1 + 3));
      upd8(best, vals, 4 * i0, 4 * i1);
    }
  }

  best = block_argmax(best);
  if (t == 0 && best.i != 0x7fffffff) {
    unsigned long long packed =
        ((unsigned long long)__float_as_uint(best.v) << 32) | (unsigned)(~best.i);
    atomicMax(&g_best[b], packed);
  }

  // ---- deterministic last-block final assembly -----------------------------------
  __threadfence();
  __shared__ bool amLast;
  if (t == 0) {
    unsigned tk = atomicAdd(&g_ticket, 1u);
    amLast = (tk == (unsigned)(kGridTotal - 1));
  }
  __syncthreads();
  if (!amLast) return;

  volatile unsigned long long* vbest = g_best;
  int bb = t;
  if (bb < kB) {
    int acc = 0, em2 = 0;
    bool alive = true;
#pragma unroll
    for (int n = 0; n < kN; n++) {
      bool a = accept_bn(bb, n, tok, dp, vp);
      acc += a ? 1 : 0;
      if (alive) { if (a) em2++; else alive = false; }
    }
    if (out_size >= kB * (kN + 1) + 2 * kB) {
      out[kB * (kN + 1) + bb] = (float)acc;
      out[kB * (kN + 1) + kB + bb] = (float)em2;
    }
    int fin = (int)(~(unsigned)(vbest[bb] & 0xffffffffu));
#pragma unroll
    for (int pos = 0; pos < kN + 1; pos++) {
      float o;
      if (pos < em2)       o = (float)tok[bb * kN + pos];
      else if (pos == em2) o = (float)fin;
      else                 o = -1.0f;
      out[bb * (kN + 1) + pos] = o;
    }
  }
  __syncthreads();
  // reset scratch for the next graph replay
  if (t < kB) g_best[t] = 0ull;
  if (t == 0) g_ticket = 0u;
}

}  // namespace

extern "C" void kernel_launch(void* const* d_in, const int* in_sizes, int n_in,
                              void* d_out, int out_size) {
  const int*   tok = nullptr;
  const float* dp  = nullptr;
  const float* vp  = nullptr;
  for (int i = 0; i < n_in; i++) {
    if (in_sizes[i] == kB * kN)                      tok = (const int*)d_in[i];
    else if (in_sizes[i] == kB * kN * kV)            dp  = (const float*)d_in[i];
    else if (in_sizes[i] == kB * (kN + 1) * kV)      vp  = (const float*)d_in[i];
  }
  float* out = (float*)d_out;

  kGumbel<<<kGridTotal, kTPB>>>(tok, dp, vp, out, out_size);
}

// round 16
// speedup vs baseline: 2.0682x; 1.0211x over previous
#include <cuda_runtime.h>
#include <cstdint>

namespace {

constexpr int kB = 64;
constexpr int kN = 8;
constexpr int kV = 128000;
constexpr int kCH = 25;                 // chunks per row; kQ4 = 1280 = 5 * 2 * 128
constexpr int kQ4 = kV / kCH / 4;       // float4s per chunk = 1280
constexpr int kTPB = 128;
constexpr int kPairIters = kQ4 / (2 * kTPB);  // 5, exact
constexpr int kGridTotal = kB * kCH;          // 1600 — every block fully active

// packed argmax: (float_bits << 32) | ~index -> atomicMax == (max val, tie: min idx)
__device__ unsigned long long g_best[kB];
__device__ unsigned g_ticket;

__device__ __forceinline__ float neg_inf() { return __int_as_float(0xff800000); }

// ---------------- JAX threefry2x32 (exact round structure) -------------------------
__device__ __forceinline__ void tfround(uint32_t& x0, uint32_t& x1, int r) {
  x0 += x1;
  x1 = __funnelshift_l(x1, x1, r);
  x1 ^= x0;
}

__device__ __forceinline__ uint2 threefry2x32(uint32_t k0, uint32_t k1,
                                              uint32_t x0, uint32_t x1) {
  uint32_t k2 = k0 ^ k1 ^ 0x1BD11BDAu;
  x0 += k0; x1 += k1;
  tfround(x0, x1, 13); tfround(x0, x1, 15); tfround(x0, x1, 26); tfround(x0, x1, 6);
  x0 += k1; x1 += k2 + 1u;
  tfround(x0, x1, 17); tfround(x0, x1, 29); tfround(x0, x1, 16); tfround(x0, x1, 24);
  x0 += k2; x1 += k0 + 2u;
  tfround(x0, x1, 13); tfround(x0, x1, 15); tfround(x0, x1, 26); tfround(x0, x1, 6);
  x0 += k0; x1 += k1 + 3u;
  tfround(x0, x1, 17); tfround(x0, x1, 29); tfround(x0, x1, 16); tfround(x0, x1, 24);
  x0 += k1; x1 += k2 + 4u;
  tfround(x0, x1, 13); tfround(x0, x1, 15); tfround(x0, x1, 26); tfround(x0, x1, 6);
  x0 += k2; x1 += k0 + 5u;
  return make_uint2(x0, x1);
}

__device__ __forceinline__ uint32_t rbits32(uint2 key, uint32_t idx) {
  uint2 o = threefry2x32(key.x, key.y, 0u, idx);
  return o.x ^ o.y;
}

__device__ __forceinline__ float uni01(uint32_t bits) {
  return __uint_as_float((bits >> 9) | 0x3f800000u) - 1.0f;
}

// t = -log(u), u = B-1, B in [1,2). Dual path (validated rel_err 0.0 since R8):
//   d = 2-B <= 0.125: degree-6 Taylor of -log(1-d)/d, rel err ~3e-7.
//   else: -__logf(u), t >= 0.1335 -> rel err <= 1.3e-6. u==0 -> t=+inf -> val 0.
__device__ __forceinline__ float tval(uint2 key, uint32_t idx) {
  uint32_t bits = rbits32(key, idx);
  float B = __uint_as_float((bits >> 9) | 0x3f800000u);
  float u = B - 1.0f;
  float d = 2.0f - B;
  float p = 0.14285714f;
  p = fmaf(p, d, 0.16666667f);
  p = fmaf(p, d, 0.2f);
  p = fmaf(p, d, 0.25f);
  p = fmaf(p, d, 0.33333333f);
  p = fmaf(p, d, 0.5f);
  p = fmaf(p, d, 1.0f);
  float ts = d * p;
  float tb = -__logf(u);
  return (d <= 0.125f) ? ts : tb;
}

struct BestPair { float v; int i; };

// Strict-'>' pairwise tree over 8 candidates: v[0..3] -> iA+{0..3},
// v[4..7] -> iB+{0..3}, iA+3 < iB. Lowest index wins ties at every level.
__device__ __forceinline__ void upd8(BestPair& best, const float* v, int iA, int iB) {
  float a0 = v[0]; int j0 = iA;
  if (v[1] > a0) { a0 = v[1]; j0 = iA + 1; }
  float a1 = v[2]; int j1 = iA + 2;
  if (v[3] > a1) { a1 = v[3]; j1 = iA + 3; }
  float a2 = v[4]; int j2 = iB;
  if (v[5] > a2) { a2 = v[5]; j2 = iB + 1; }
  float a3 = v[6]; int j3 = iB + 2;
  if (v[7] > a3) { a3 = v[7]; j3 = iB + 3; }
  if (a1 > a0) { a0 = a1; j0 = j1; }
  if (a3 > a2) { a2 = a3; j2 = j3; }
  if (a2 > a0) { a0 = a2; j0 = j2; }
  if (a0 > best.v) { best.v = a0; best.i = j0; }
}

// Block argmax (128 threads, tie-break min index); thread 0 holds the result.
__device__ __forceinline__ BestPair block_argmax(BestPair best) {
  __shared__ float sv[4];
  __shared__ int   si[4];
  unsigned full = 0xffffffffu;
#pragma unroll
  for (int off = 16; off > 0; off >>= 1) {
    float ov = __shfl_down_sync(full, best.v, off);
    int   oi = __shfl_down_sync(full, best.i, off);
    if (ov > best.v || (ov == best.v && oi < best.i)) { best.v = ov; best.i = oi; }
  }
  int warp = threadIdx.x >> 5;
  int lane = threadIdx.x & 31;
  if (lane == 0) { sv[warp] = best.v; si[warp] = best.i; }
  __syncthreads();
  if (threadIdx.x == 0) {
#pragma unroll
    for (int w = 1; w < 4; w++) {
      if (sv[w] > best.v || (sv[w] == best.v && si[w] < best.i)) {
        best.v = sv[w]; best.i = si[w];
      }
    }
  }
  return best;
}

// accept decision for (b, n)
__device__ __forceinline__ bool accept_bn(int b, int n, const int* __restrict__ tok,
                                          const float* __restrict__ dp,
                                          const float* __restrict__ vp) {
  uint2 ku = threefry2x32(0u, 1u, 0u, 0u);   // split(key(1),3)[0] — const-folded
  int L = b * kN + n;
  float u = uni01(rbits32(ku, (uint32_t)L));
  int t = tok[L];
  t = min(max(t, 0), kV - 1);
  float q = dp[(size_t)L * kV + t];
  float p = vp[((size_t)b * (kN + 1) + n) * kV + t];
  return (u * q < p);
}

// ---------------- Single mega kernel: one block per (batch, chunk), all active -----
// launch_bounds(128, 11): 148*11 = 1628 >= 1600 (still one wave) but reg budget
// rises 32 -> 46, letting ptxas keep 8 threefry chains genuinely in flight.
__global__ __launch_bounds__(kTPB, 11)
void kGumbel(const int* __restrict__ tok, const float* __restrict__ dp,
             const float* __restrict__ vp, float* __restrict__ out,
             int out_size) {
  __shared__ int s_em;
  int blk = blockIdx.x;
  int b = blk / kCH;
  int c = blk % kCH;
  int t = threadIdx.x;

  // em for this batch (lanes 0..7 + ballot)
  if (t < 8) {
    bool acc = accept_bn(b, t, tok, dp, vp);
    unsigned m = __ballot_sync(0xffu, acc);
    if (t == 0) s_em = __ffs((~m) & 0x1FF) - 1;
  }
  __syncthreads();
  int em = s_em;

  BestPair best = {neg_inf(), 0x7fffffff};
  int base = c * kQ4 + t;

  if (em >= kN) {
    // ---- bonus: argmax over verify[b, N, :] -------------------------------------
    uint2 kb = threefry2x32(0u, 1u, 0u, 2u);   // subkey 2 (const-folded)
    const float4* row = (const float4*)(vp + ((size_t)b * (kN + 1) + kN) * kV);
    uint32_t Lbase = (uint32_t)b * (uint32_t)kV;   // gumbel shape (B, V)
#pragma unroll 1
    for (int k = 0; k < kPairIters; k++) {
      int i0 = base + k * 2 * kTPB;
      int i1 = i0 + kTPB;
      float4 pa = row[i0];
      float4 pb = row[i1];
      // batch the 8 independent threefry chains first, then the 8 divides
      float tv[8];
      tv[0] = tval(kb, Lbase + 4 * i0 + 0);
      tv[1] = tval(kb, Lbase + 4 * i0 + 1);
      tv[2] = tval(kb, Lbase + 4 * i0 + 2);
      tv[3] = tval(kb, Lbase + 4 * i0 + 3);
      tv[4] = tval(kb, Lbase + 4 * i1 + 0);
      tv[5] = tval(kb, Lbase + 4 * i1 + 1);
      tv[6] = tval(kb, Lbase + 4 * i1 + 2);
      tv[7] = tval(kb, Lbase + 4 * i1 + 3);
      float vals[8];
      vals[0] = __fdividef(pa.x, tv[0]);
      vals[1] = __fdividef(pa.y, tv[1]);
      vals[2] = __fdividef(pa.z, tv[2]);
      vals[3] = __fdividef(pa.w, tv[3]);
      vals[4] = __fdividef(pb.x, tv[4]);
      vals[5] = __fdividef(pb.y, tv[5]);
      vals[6] = __fdividef(pb.z, tv[6]);
      vals[7] = __fdividef(pb.w, tv[7]);
      upd8(best, vals, 4 * i0, 4 * i1);
    }
  } else {
    // ---- recover: argmax over relu(verify[b,em]-draft[b,em]) --------------------
    uint2 kr = threefry2x32(0u, 1u, 0u, 1u);   // subkey 1 (const-folded)
    const float4* drow = (const float4*)(dp + ((size_t)b * kN + em) * kV);
    const float4* vrow = (const float4*)(vp + ((size_t)b * (kN + 1) + em) * kV);
    uint32_t Lbase = (uint32_t)(b * kN + em) * (uint32_t)kV;   // shape (B, N, V)
#pragma unroll 1
    for (int k = 0; k < kPairIters; k++) {
      int i0 = base + k * 2 * kTPB;
      int i1 = i0 + kTPB;
      float4 da = drow[i0];
      float4 va = vrow[i0];
      float4 db = drow[i1];
      float4 vb = vrow[i1];
      float tv[8];
      tv[0] = tval(kr, Lbase + 4 * i0 + 0);
      tv[1] = tval(kr, Lbase + 4 * i0 + 1);
      tv[2] = tval(kr, Lbase + 4 * i0 + 2);
      tv[3] = tval(kr, Lbase + 4 * i0 + 3);
      tv[4] = tval(kr, Lbase + 4 * i1 + 0);
      tv[5] = tval(kr, Lbase + 4 * i1 + 1);
      tv[6] = tval(kr, Lbase + 4 * i1 + 2);
      tv[7] = tval(kr, Lbase + 4 * i1 + 3);
      float vals[8];
      vals[0] = __fdividef(fmaxf(va.x - da.x, 0.0f), tv[0]);
      vals[1] = __fdividef(fmaxf(va.y - da.y, 0.0f), tv[1]);
      vals[2] = __fdividef(fmaxf(va.z - da.z, 0.0f), tv[2]);
      vals[3] = __fdividef(fmaxf(va.w - da.w, 0.0f), tv[3]);
      vals[4] = __fdividef(fmaxf(vb.x - db.x, 0.0f), tv[4]);
      vals[5] = __fdividef(fmaxf(vb.y - db.y, 0.0f), tv[5]);
      vals[6] = __fdividef(fmaxf(vb.z - db.z, 0.0f), tv[6]);
      vals[7] = __fdividef(fmaxf(vb.w - db.w, 0.0f), tv[7]);
      upd8(best, vals, 4 * i0, 4 * i1);
    }
  }

  best = block_argmax(best);
  if (t == 0 && best.i != 0x7fffffff) {
    unsigned long long packed =
        ((unsigned long long)__float_as_uint(best.v) << 32) | (unsigned)(~best.i);
    atomicMax(&g_best[b], packed);
  }

  // ---- deterministic last-block final assembly -----------------------------------
  __threadfence();
  __shared__ bool amLast;
  if (t == 0) {
    unsigned tk = atomicAdd(&g_ticket, 1u);
    amLast = (tk == (unsigned)(kGridTotal - 1));
  }
  __syncthreads();
  if (!amLast) return;

  volatile unsigned long long* vbest = g_best;
  int bb = t;
  if (bb < kB) {
    int acc = 0, em2 = 0;
    bool alive = true;
#pragma unroll
    for (int n = 0; n < kN; n++) {
      bool a = accept_bn(bb, n, tok, dp, vp);
      acc += a ? 1 : 0;
      if (alive) { if (a) em2++; else alive = false; }
    }
    if (out_size >= kB * (kN + 1) + 2 * kB) {
      out[kB * (kN + 1) + bb] = (float)acc;
      out[kB * (kN + 1) + kB + bb] = (float)em2;
    }
    int fin = (int)(~(unsigned)(vbest[bb] & 0xffffffffu));
#pragma unroll
    for (int pos = 0; pos < kN + 1; pos++) {
      float o;
      if (pos < em2)       o = (float)tok[bb * kN + pos];
      else if (pos == em2) o = (float)fin;
      else                 o = -1.0f;
      out[bb * (kN + 1) + pos] = o;
    }
  }
  __syncthreads();
  // reset scratch for the next graph replay
  if (t < kB) g_best[t] = 0ull;
  if (t == 0) g_ticket = 0u;
}

}  // namespace

extern "C" void kernel_launch(void* const* d_in, const int* in_sizes, int n_in,
                              void* d_out, int out_size) {
  const int*   tok = nullptr;
  const float* dp  = nullptr;
  const float* vp  = nullptr;
  for (int i = 0; i < n_in; i++) {
    if (in_sizes[i] == kB * kN)                      tok = (const int*)d_in[i];
    else if (in_sizes[i] == kB * kN * kV)            dp  = (const float*)d_in[i];
    else if (in_sizes[i] == kB * (kN + 1) * kV)      vp  = (const float*)d_in[i];
  }
  float* out = (float*)d_out;

  kGumbel<<<kGridTotal, kTPB>>>(tok, dp, vp, out, out_size);
}

// round 17
// speedup vs baseline: 2.1037x; 1.0171x over previous
#include <cuda_runtime.h>
#include <cstdint>

namespace {

constexpr int kB = 64;
constexpr int kN = 8;
constexpr int kV = 128000;
constexpr int kCH = 25;                 // chunks per row; kQ4 = 1280 = 5 * 2 * 128
constexpr int kQ4 = kV / kCH / 4;       // float4s per chunk = 1280
constexpr int kTPB = 128;
constexpr int kPairIters = kQ4 / (2 * kTPB);  // 5, exact
constexpr int kGridTotal = kB * kCH;          // 1600 — every block fully active
constexpr int kOutTok = kB * (kN + 1);        // 576
constexpr int kOutFull = kOutTok + 2 * kB;    // 704

// packed argmax: (float_bits << 32) | ~index -> atomicMax == (max val, tie: min idx)
__device__ unsigned long long g_best[kB];
__device__ unsigned g_ticket;

__device__ __forceinline__ float neg_inf() { return __int_as_float(0xff800000); }

// ---------------- JAX threefry2x32 (exact round structure) -------------------------
__device__ __forceinline__ void tfround(uint32_t& x0, uint32_t& x1, int r) {
  x0 += x1;
  x1 = __funnelshift_l(x1, x1, r);
  x1 ^= x0;
}

__device__ __forceinline__ uint2 threefry2x32(uint32_t k0, uint32_t k1,
                                              uint32_t x0, uint32_t x1) {
  uint32_t k2 = k0 ^ k1 ^ 0x1BD11BDAu;
  x0 += k0; x1 += k1;
  tfround(x0, x1, 13); tfround(x0, x1, 15); tfround(x0, x1, 26); tfround(x0, x1, 6);
  x0 += k1; x1 += k2 + 1u;
  tfround(x0, x1, 17); tfround(x0, x1, 29); tfround(x0, x1, 16); tfround(x0, x1, 24);
  x0 += k2; x1 += k0 + 2u;
  tfround(x0, x1, 13); tfround(x0, x1, 15); tfround(x0, x1, 26); tfround(x0, x1, 6);
  x0 += k0; x1 += k1 + 3u;
  tfround(x0, x1, 17); tfround(x0, x1, 29); tfround(x0, x1, 16); tfround(x0, x1, 24);
  x0 += k1; x1 += k2 + 4u;
  tfround(x0, x1, 13); tfround(x0, x1, 15); tfround(x0, x1, 26); tfround(x0, x1, 6);
  x0 += k2; x1 += k0 + 5u;
  return make_uint2(x0, x1);
}

__device__ __forceinline__ uint32_t rbits32(uint2 key, uint32_t idx) {
  uint2 o = threefry2x32(key.x, key.y, 0u, idx);
  return o.x ^ o.y;
}

__device__ __forceinline__ float uni01(uint32_t bits) {
  return __uint_as_float((bits >> 9) | 0x3f800000u) - 1.0f;
}

// t = -log(u), u = B-1, B in [1,2). Dual path (validated rel_err 0.0 since R8):
//   d = 2-B <= 0.125: degree-6 Taylor of -log(1-d)/d, rel err ~3e-7.
//   else: -__logf(u), t >= 0.1335 -> rel err <= 1.3e-6. u==0 -> t=+inf -> val 0.
__device__ __forceinline__ float tval(uint2 key, uint32_t idx) {
  uint32_t bits = rbits32(key, idx);
  float B = __uint_as_float((bits >> 9) | 0x3f800000u);
  float u = B - 1.0f;
  float d = 2.0f - B;
  float p = 0.14285714f;
  p = fmaf(p, d, 0.16666667f);
  p = fmaf(p, d, 0.2f);
  p = fmaf(p, d, 0.25f);
  p = fmaf(p, d, 0.33333333f);
  p = fmaf(p, d, 0.5f);
  p = fmaf(p, d, 1.0f);
  float ts = d * p;
  float tb = -__logf(u);
  return (d <= 0.125f) ? ts : tb;
}

struct BestPair { float v; int i; };

// Strict-'>' pairwise tree over 8 candidates: v[0..3] -> iA+{0..3},
// v[4..7] -> iB+{0..3}, iA+3 < iB. Lowest index wins ties at every level.
__device__ __forceinline__ void upd8(BestPair& best, const float* v, int iA, int iB) {
  float a0 = v[0]; int j0 = iA;
  if (v[1] > a0) { a0 = v[1]; j0 = iA + 1; }
  float a1 = v[2]; int j1 = iA + 2;
  if (v[3] > a1) { a1 = v[3]; j1 = iA + 3; }
  float a2 = v[4]; int j2 = iB;
  if (v[5] > a2) { a2 = v[5]; j2 = iB + 1; }
  float a3 = v[6]; int j3 = iB + 2;
  if (v[7] > a3) { a3 = v[7]; j3 = iB + 3; }
  if (a1 > a0) { a0 = a1; j0 = j1; }
  if (a3 > a2) { a2 = a3; j2 = j3; }
  if (a2 > a0) { a0 = a2; j0 = j2; }
  if (a0 > best.v) { best.v = a0; best.i = j0; }
}

// Block argmax (128 threads, tie-break min index); thread 0 holds the result.
__device__ __forceinline__ BestPair block_argmax(BestPair best) {
  __shared__ float sv[4];
  __shared__ int   si[4];
  unsigned full = 0xffffffffu;
#pragma unroll
  for (int off = 16; off > 0; off >>= 1) {
    float ov = __shfl_down_sync(full, best.v, off);
    int   oi = __shfl_down_sync(full, best.i, off);
    if (ov > best.v || (ov == best.v && oi < best.i)) { best.v = ov; best.i = oi; }
  }
  int warp = threadIdx.x >> 5;
  int lane = threadIdx.x & 31;
  if (lane == 0) { sv[warp] = best.v; si[warp] = best.i; }
  __syncthreads();
  if (threadIdx.x == 0) {
#pragma unroll
    for (int w = 1; w < 4; w++) {
      if (sv[w] > best.v || (sv[w] == best.v && si[w] < best.i)) {
        best.v = sv[w]; best.i = si[w];
      }
    }
  }
  return best;
}

// accept decision for (b, n)
__device__ __forceinline__ bool accept_bn(int b, int n, const int* __restrict__ tok,
                                          const float* __restrict__ dp,
                                          const float* __restrict__ vp) {
  uint2 ku = threefry2x32(0u, 1u, 0u, 0u);   // split(key(1),3)[0] — const-folded
  int L = b * kN + n;
  float u = uni01(rbits32(ku, (uint32_t)L));
  int t = tok[L];
  t = min(max(t, 0), kV - 1);
  float q = dp[(size_t)L * kV + t];
  float p = vp[((size_t)b * (kN + 1) + n) * kV + t];
  return (u * q < p);
}

// ---------------- Single mega kernel: one block per (batch, chunk), all active -----
// Per-warp em (full-warp ballot, no __syncthreads). Chunk-0 blocks write acc/em and
// all static output positions; the ticket block only writes the final token per
// batch (reads em back from out — ordered by fence + ticket).
__global__ __launch_bounds__(kTPB, 11)
void kGumbel(const int* __restrict__ tok, const float* __restrict__ dp,
             const float* __restrict__ vp, float* __restrict__ out,
             int out_size) {
  int blk = blockIdx.x;
  int b = blk / kCH;
  int c = blk % kCH;
  int t = threadIdx.x;
  int lane = t & 31;

  // ---- per-warp em: every lane computes accept(n = lane&7); full ballot ----------
  bool a = accept_bn(b, lane & 7, tok, dp, vp);
  unsigned m = __ballot_sync(0xffffffffu, a) & 0xFFu;   // bits repeat every 8 lanes
  int em = __ffs((~m) & 0x1FFu) - 1;                    // leading-accept count, 8 max

  // ---- chunk-0 block: write acc/em and static token positions --------------------
  if (c == 0 && t < 32) {
    if (out_size >= kOutFull) {
      if (t == 9)  out[kOutTok + b] = (float)__popc(m);        // accepted_token_num
      if (t == 10) out[kOutTok + kB + b] = (float)em;          // emitted_token_num
    }
    if (t < kN + 1 && t != em)
      out[b * (kN + 1) + t] = (t < em) ? (float)tok[b * kN + t] : -1.0f;
  }

  BestPair best = {neg_inf(), 0x7fffffff};
  int base = c * kQ4 + t;

  if (em >= kN) {
    // ---- bonus: argmax over verify[b, N, :] -------------------------------------
    uint2 kb = threefry2x32(0u, 1u, 0u, 2u);   // subkey 2 (const-folded)
    const float4* row = (const float4*)(vp + ((size_t)b * (kN + 1) + kN) * kV);
    uint32_t Lbase = (uint32_t)b * (uint32_t)kV;   // gumbel shape (B, V)
#pragma unroll 1
    for (int k = 0; k < kPairIters; k++) {
      int i0 = base + k * 2 * kTPB;
      int i1 = i0 + kTPB;
      float4 pa = row[i0];
      float4 pb = row[i1];
      float tv[8];
      tv[0] = tval(kb, Lbase + 4 * i0 + 0);
      tv[1] = tval(kb, Lbase + 4 * i0 + 1);
      tv[2] = tval(kb, Lbase + 4 * i0 + 2);
      tv[3] = tval(kb, Lbase + 4 * i0 + 3);
      tv[4] = tval(kb, Lbase + 4 * i1 + 0);
      tv[5] = tval(kb, Lbase + 4 * i1 + 1);
      tv[6] = tval(kb, Lbase + 4 * i1 + 2);
      tv[7] = tval(kb, Lbase + 4 * i1 + 3);
      float vals[8];
      vals[0] = __fdividef(pa.x, tv[0]);
      vals[1] = __fdividef(pa.y, tv[1]);
      vals[2] = __fdividef(pa.z, tv[2]);
      vals[3] = __fdividef(pa.w, tv[3]);
      vals[4] = __fdividef(pb.x, tv[4]);
      vals[5] = __fdividef(pb.y, tv[5]);
      vals[6] = __fdividef(pb.z, tv[6]);
      vals[7] = __fdividef(pb.w, tv[7]);
      upd8(best, vals, 4 * i0, 4 * i1);
    }
  } else {
    // ---- recover: argmax over relu(verify[b,em]-draft[b,em]) --------------------
    uint2 kr = threefry2x32(0u, 1u, 0u, 1u);   // subkey 1 (const-folded)
    const float4* drow = (const float4*)(dp + ((size_t)b * kN + em) * kV);
    const float4* vrow = (const float4*)(vp + ((size_t)b * (kN + 1) + em) * kV);
    uint32_t Lbase = (uint32_t)(b * kN + em) * (uint32_t)kV;   // shape (B, N, V)
#pragma unroll 1
    for (int k = 0; k < kPairIters; k++) {
      int i0 = base + k * 2 * kTPB;
      int i1 = i0 + kTPB;
      float4 da = drow[i0];
      float4 va = vrow[i0];
      float4 db = drow[i1];
      float4 vb = vrow[i1];
      float tv[8];
      tv[0] = tval(kr, Lbase + 4 * i0 + 0);
      tv[1] = tval(kr, Lbase + 4 * i0 + 1);
      tv[2] = tval(kr, Lbase + 4 * i0 + 2);
      tv[3] = tval(kr, Lbase + 4 * i0 + 3);
      tv[4] = tval(kr, Lbase + 4 * i1 + 0);
      tv[5] = tval(kr, Lbase + 4 * i1 + 1);
      tv[6] = tval(kr, Lbase + 4 * i1 + 2);
      tv[7] = tval(kr, Lbase + 4 * i1 + 3);
      float vals[8];
      vals[0] = __fdividef(fmaxf(va.x - da.x, 0.0f), tv[0]);
      vals[1] = __fdividef(fmaxf(va.y - da.y, 0.0f), tv[1]);
      vals[2] = __fdividef(fmaxf(va.z - da.z, 0.0f), tv[2]);
      vals[3] = __fdividef(fmaxf(va.w - da.w, 0.0f), tv[3]);
      vals[4] = __fdividef(fmaxf(vb.x - db.x, 0.0f), tv[4]);
      vals[5] = __fdividef(fmaxf(vb.y - db.y, 0.0f), tv[5]);
      vals[6] = __fdividef(fmaxf(vb.z - db.z, 0.0f), tv[6]);
      vals[7] = __fdividef(fmaxf(vb.w - db.w, 0.0f), tv[7]);
      upd8(best, vals, 4 * i0, 4 * i1);
    }
  }

  best = block_argmax(best);
  if (t == 0 && best.i != 0x7fffffff) {
    unsigned long long packed =
        ((unsigned long long)__float_as_uint(best.v) << 32) | (unsigned)(~best.i);
    atomicMax(&g_best[b], packed);
  }

  // ---- deterministic last-block final assembly (tiny tail) -------------------------
  __threadfence();
  __shared__ bool amLast;
  if (t == 0) {
    unsigned tk = atomicAdd(&g_ticket, 1u);
    amLast = (tk == (unsigned)(kGridTotal - 1));
  }
  __syncthreads();
  if (!amLast) return;

  volatile unsigned long long* vbest = g_best;
  volatile float* vout = out;
  int bb = t;
  if (bb < kB) {
    int em2;
    if (out_size >= kOutFull) {
      em2 = (int)vout[kOutTok + kB + bb];      // written by chunk-0 block, fenced
    } else {
      // defensive fallback (not taken with the standard 704-element output)
      em2 = 0;
      bool alive = true;
#pragma unroll
      for (int n = 0; n < kN; n++) {
        bool aa = accept_bn(bb, n, tok, dp, vp);
        if (alive) { if (aa) em2++; else alive = false; }
      }
    }
    int fin = (int)(~(unsigned)(vbest[bb] & 0xffffffffu));
    out[bb * (kN + 1) + em2] = (float)fin;
  }
  __syncthreads();
  // reset scratch for the next graph replay
  if (t < kB) g_best[t] = 0ull;
  if (t == 0) g_ticket = 0u;
}

}  // namespace

extern "C" void kernel_launch(void* const* d_in, const int* in_sizes, int n_in,
                              void* d_out, int out_size) {
  const int*   tok = nullptr;
  const float* dp  = nullptr;
  const float* vp  = nullptr;
  for (int i = 0; i < n_in; i++) {
    if (in_sizes[i] == kB * kN)                      tok = (const int*)d_in[i];
    else if (in_sizes[i] == kB * kN * kV)            dp  = (const float*)d_in[i];
    else if (in_sizes[i] == kB * (kN + 1) * kV)      vp  = (const float*)d_in[i];
  }
  float* out = (float*)d_out;

  kGumbel<<<kGridTotal, kTPB>>>(tok, dp, vp, out, out_size);
}